// round 8
// baseline (speedup 1.0000x reference)
#include <cuda_runtime.h>
#include <cstdint>

// Problem constants (fixed by the reference: x,y are [8192, 1024] fp32)
#define N_ROWS 8192
#define D      1024
#define ROW_BYTES (D * 4)                   // 4096
#define ROWS_PER_BLOCK 8
#define NUM_BLOCKS (N_ROWS / ROWS_PER_BLOCK) // 1024
#define NSTAGE 3                            // smem buffer ring depth
#define NWARPS 9                            // 8 consumer + 1 producer
#define BLOCK_THREADS (NWARPS * 32)         // 288

__device__ float g_partials[NUM_BLOCKS];
__device__ unsigned int g_counter = 0;

// ---- small PTX helpers -------------------------------------------------
__device__ __forceinline__ uint32_t s2u(const void* p) {
    uint32_t a;
    asm("{ .reg .u64 t; cvta.to.shared.u64 t, %1; cvt.u32.u64 %0, t; }"
        : "=r"(a) : "l"(p));
    return a;
}
__device__ __forceinline__ void mbar_init(uint32_t m, uint32_t cnt) {
    asm volatile("mbarrier.init.shared.b64 [%0], %1;" :: "r"(m), "r"(cnt) : "memory");
}
__device__ __forceinline__ void mbar_expect_tx(uint32_t m, uint32_t bytes) {
    asm volatile("mbarrier.arrive.expect_tx.shared.b64 _, [%0], %1;"
                 :: "r"(m), "r"(bytes) : "memory");
}
__device__ __forceinline__ void mbar_arrive(uint32_t m) {
    asm volatile("mbarrier.arrive.shared.b64 _, [%0];" :: "r"(m) : "memory");
}
__device__ __forceinline__ void mbar_wait(uint32_t m, uint32_t parity) {
    uint32_t done;
    do {
        asm volatile(
            "{\n\t.reg .pred p;\n\t"
            "mbarrier.try_wait.parity.acquire.cta.shared::cta.b64 p, [%1], %2, 0x989680;\n\t"
            "selp.b32 %0, 1, 0, p;\n\t}"
            : "=r"(done) : "r"(m), "r"(parity) : "memory");
    } while (!done);
}
// 1D bulk async copy global -> shared::cta, completion via mbarrier tx-bytes.
__device__ __forceinline__ void bulk_g2s(uint32_t dst, const void* src,
                                         uint32_t bytes, uint32_t mbar) {
    asm volatile(
        "cp.async.bulk.shared::cta.global.mbarrier::complete_tx::bytes [%0], [%1], %2, [%3];"
        :: "r"(dst), "l"(src), "r"(bytes), "r"(mbar) : "memory");
}
// ------------------------------------------------------------------------

__global__ __launch_bounds__(BLOCK_THREADS)
void row_loss_bulk_kernel(const float* __restrict__ x,
                          const float* __restrict__ y,
                          float* __restrict__ out) {
    // 3-deep ring of row-pair buffers: 3 * (4KB + 4KB) = 24KB.
    __shared__ alignas(128) float bufx[NSTAGE][D];
    __shared__ alignas(128) float bufy[NSTAGE][D];
    // Single-use barriers per row (no parity aliasing): full = data landed,
    // done = consumer finished reading (buffer reusable).
    __shared__ uint64_t full_mb[ROWS_PER_BLOCK];
    __shared__ uint64_t done_mb[ROWS_PER_BLOCK];
    __shared__ float s_loss[ROWS_PER_BLOCK];

    const int tid  = threadIdx.x;
    const int warp = tid >> 5;
    const int lane = tid & 31;

    if (tid == 0) {
        #pragma unroll
        for (int i = 0; i < ROWS_PER_BLOCK; i++) {
            mbar_init(s2u(&full_mb[i]), 1);
            mbar_init(s2u(&done_mb[i]), 1);
        }
    }
    __syncthreads();

    if (warp == 8) {
        // Producer: one elected thread streams all 8 row-pairs through the ring.
        if (lane == 0) {
            const size_t base = (size_t)blockIdx.x * ROWS_PER_BLOCK;
            #pragma unroll
            for (int i = 0; i < ROWS_PER_BLOCK; i++) {
                const int s = i % NSTAGE;
                if (i >= NSTAGE)
                    mbar_wait(s2u(&done_mb[i - NSTAGE]), 0);  // buffer s free
                const uint32_t fm = s2u(&full_mb[i]);
                mbar_expect_tx(fm, 2 * ROW_BYTES);
                bulk_g2s(s2u(&bufx[s][0]), x + (base + i) * D, ROW_BYTES, fm);
                bulk_g2s(s2u(&bufy[s][0]), y + (base + i) * D, ROW_BYTES, fm);
            }
        }
    } else {
        // Consumer warp w owns row (block*8 + w), staged in buffer w%NSTAGE.
        const int s = warp % NSTAGE;
        mbar_wait(s2u(&full_mb[warp]), 0);

        const float4* __restrict__ xa = reinterpret_cast<const float4*>(&bufx[s][0]);
        const float4* __restrict__ ya = reinterpret_cast<const float4*>(&bufy[s][0]);

        float dot = 0.0f, xx = 0.0f, yy = 0.0f;
        #pragma unroll
        for (int k = 0; k < 8; k++) {
            float4 a = xa[lane + 32 * k];
            float4 b = ya[lane + 32 * k];
            dot += a.x * b.x + a.y * b.y + a.z * b.z + a.w * b.w;
            xx  += a.x * a.x + a.y * a.y + a.z * a.z + a.w * a.w;
            yy  += b.x * b.x + b.y * b.y + b.z * b.z + b.w * b.w;
        }

        #pragma unroll
        for (int off = 16; off > 0; off >>= 1) {
            dot += __shfl_down_sync(0xFFFFFFFFu, dot, off);
            xx  += __shfl_down_sync(0xFFFFFFFFu, xx,  off);
            yy  += __shfl_down_sync(0xFFFFFFFFu, yy,  off);
        }
        __syncwarp();
        if (lane == 0) {
            float inv_norm = rsqrtf(fmaxf(xx * yy, 1e-24f));
            float cosv = dot * inv_norm;
            float arg  = fmaxf((cosv + 1.0f) * 0.5f, 1e-30f);
            s_loss[warp] = -logf(arg);
            mbar_arrive(s2u(&done_mb[warp]));  // release: reads done, buffer free
        }
    }
    __syncthreads();

    __shared__ bool s_is_last;
    if (tid == 0) {
        float t = 0.0f;
        #pragma unroll
        for (int i = 0; i < ROWS_PER_BLOCK; i++) t += s_loss[i];
        g_partials[blockIdx.x] = t;
        __threadfence();
        unsigned int prev = atomicAdd(&g_counter, 1u);
        s_is_last = (prev == (unsigned int)(NUM_BLOCKS - 1));
    }
    __syncthreads();

    // Single last-arriving block: deterministic fixed-order reduction of all
    // partials; re-arms the counter for the next graph replay.
    if (s_is_last) {
        float v = 0.0f;
        #pragma unroll
        for (int i = 0; i < NUM_BLOCKS / 256; i++) {
            int idx = tid + i * 256;
            if (idx < NUM_BLOCKS && tid < 256) v += g_partials[idx];
        }
        #pragma unroll
        for (int off = 16; off > 0; off >>= 1)
            v += __shfl_down_sync(0xFFFFFFFFu, v, off);

        __shared__ float s_fin[NWARPS];
        if (lane == 0) s_fin[warp] = v;
        __syncthreads();

        if (tid == 0) {
            float t = 0.0f;
            #pragma unroll
            for (int i = 0; i < NWARPS; i++) t += s_fin[i];
            out[0] = t * (1.0f / (float)N_ROWS);
            g_counter = 0;
        }
    }
}

extern "C" void kernel_launch(void* const* d_in, const int* in_sizes, int n_in,
                              void* d_out, int out_size) {
    const float* x = (const float*)d_in[0];
    const float* y = (const float*)d_in[1];
    float* out = (float*)d_out;

    row_loss_bulk_kernel<<<NUM_BLOCKS, BLOCK_THREADS>>>(x, y, out);
}